// round 16
// baseline (speedup 1.0000x reference)
#include <cuda_runtime.h>
#include <cuda_fp16.h>
#include <math.h>

// DualModeSinkhorn — factorized Sinkhorn: Hl = E .* (R ⊗ C).
// R15: persistent kernel retired (2x consecutive container failures; multi-
// launch ran 4/4). Merged single grid over all 32 batches, made L2-resident by
// storing the conv marginals M,N in fp16 (R,C stay fp32):
//   iteration set = E(fp16) 67MB + R,C(fp32) 33.5MB + M,N(fp16) 16.8MB = 117MB < 126MB L2.
// 41 plain launches total (vs 82), static smem only, no attribute calls.

#define HW      16384           // 128*128
#define EPSF    1e-8f
#define NB      32
#define NITER   20
#define TPB     256
#define GRID    ((NB * HW) / TPB)   // 2048 blocks

// Scratch (static device globals — no runtime allocation)
__device__ __half2 g_Eh[(size_t)NB * HW * 32];  // exp(input) fp16, layout [b][p][i*8+j]
__device__ __half  g_M[(size_t)NB * 8 * HW];    // row marginal (fp16)
__device__ __half  g_N[(size_t)NB * 8 * HW];    // col marginal (fp16)
__device__ float   g_R[(size_t)NB * 8 * HW];    // row scale factors (fp32)
__device__ float   g_C[(size_t)NB * 8 * HW];    // col scale factors (fp32)

// ---------------------------------------------------------------------------
// 5x5 circular Gaussian conv of the 8-channel fp16 (128,128) marginal at this
// block's 8x32 tile. Separable: k = ay ⊗ ax. smem is fp32, row stride 40:
// interior cols at idx 4..35 (16B-aligned), halos at idx 2,3 and 36,37.
// ---------------------------------------------------------------------------
__device__ __forceinline__ void conv8h(
    const __half* __restrict__ cin_b,      // marginal base for this batch (8 planes)
    unsigned tid, unsigned tx, unsigned ty, unsigned h0, unsigned w0,
    const float* ax, const float* ay,
    float* s_in, float* s_h,
    float outv[8])
{
    // Interior: 8ch x 12 rows x 4 uint4 (8 halves each).
    for (unsigned q = tid; q < 384u; q += TPB) {
        unsigned row_id = q >> 2;              // ch*12 + hh, 0..95
        unsigned quad   = q & 3u;
        unsigned ch     = row_id / 12u;
        unsigned hh     = row_id - ch * 12u;
        unsigned gh     = (h0 + hh - 2u) & 127u;
        uint4 v = *reinterpret_cast<const uint4*>(
            cin_b + (ch << 14) + (gh << 7) + w0 + (quad << 3));
        const __half2* hp = reinterpret_cast<const __half2*>(&v);
        float2 f0 = __half22float2(hp[0]);
        float2 f1 = __half22float2(hp[1]);
        float2 f2 = __half22float2(hp[2]);
        float2 f3 = __half22float2(hp[3]);
        float* dst = s_in + ch * 480u + hh * 40u + 4u + (quad << 3);
        reinterpret_cast<float4*>(dst)[0] = make_float4(f0.x, f0.y, f1.x, f1.y);
        reinterpret_cast<float4*>(dst)[1] = make_float4(f2.x, f2.y, f3.x, f3.y);
    }
    // Edges: 96 rows x 2 aligned half2 (left pair w0-2,w0-1; right pair w0+32,w0+33).
    for (unsigned e = tid; e < 192u; e += TPB) {
        unsigned row_id = e >> 1;
        unsigned side   = e & 1u;
        unsigned ch     = row_id / 12u;
        unsigned hh     = row_id - ch * 12u;
        unsigned gh     = (h0 + hh - 2u) & 127u;
        unsigned gw = side ? ((w0 + 32u) & 127u) : ((w0 - 2u) & 127u);  // even => aligned
        unsigned si = side ? 36u : 2u;
        __half2 hv = *reinterpret_cast<const __half2*>(cin_b + (ch << 14) + (gh << 7) + gw);
        float2 f = __half22float2(hv);
        float* dst = s_in + ch * 480u + hh * 40u + si;
        dst[0] = f.x; dst[1] = f.y;
    }
    __syncthreads();

    // Horizontal pass: (12 x 32) per channel.
    for (unsigned e = tid; e < 3072u; e += TPB) {
        unsigned ch = e / 384u;
        unsigned r  = e - ch * 384u;
        unsigned hh = r >> 5;
        unsigned ww = r & 31u;
        const float* row = &s_in[ch * 480u + hh * 40u + 2u + ww];
        s_h[ch * 384u + (hh << 5) + ww] = ax[0] * row[0] + ax[1] * row[1] + ax[2] * row[2]
                                        + ax[3] * row[3] + ax[4] * row[4];
    }
    __syncthreads();

#pragma unroll
    for (int i = 0; i < 8; ++i) {
        const float* col = &s_h[i * 384u + (ty << 5) + tx];
        outv[i] = ay[0] * col[0] + ay[1] * col[32] + ay[2] * col[64]
                + ay[3] * col[96] + ay[4] * col[128];
    }
}

__device__ __forceinline__ void load_taps(const float* __restrict__ kern,
                                          float* ax, float* ay)
{
#pragma unroll
    for (int d = 0; d < 5; ++d) {
        ax[d] = __ldg(kern + d) + __ldg(kern + 5 + d) + __ldg(kern + 10 + d)
              + __ldg(kern + 15 + d) + __ldg(kern + 20 + d);
        ay[d] = __ldg(kern + 5 * d) + __ldg(kern + 5 * d + 1) + __ldg(kern + 5 * d + 2)
              + __ldg(kern + 5 * d + 3) + __ldg(kern + 5 * d + 4);
    }
}

// ---------------------------------------------------------------------------
// Prologue: E(fp16, interleaved) = exp(input); M(fp16) = row-sums; R = C = 1.
// ---------------------------------------------------------------------------
__global__ void __launch_bounds__(TPB) k_first(const float* __restrict__ in)
{
    unsigned idx = blockIdx.x * (unsigned)TPB + threadIdx.x;   // 0 .. NB*HW-1
    unsigned b   = idx >> 14;
    unsigned p   = idx & (HW - 1);

    const float* ip  = in + ((size_t)b << 20) + p;                    // b*64*HW
    uint4*       ep4 = reinterpret_cast<uint4*>(g_Eh + ((size_t)(b * HW + p) << 5));
    unsigned     mb  = (b << 17) + p;                                  // b*8*HW

#pragma unroll
    for (int i = 0; i < 8; ++i) {
        float m = 0.f;
        __half2 h[4];
#pragma unroll
        for (int jj = 0; jj < 4; ++jj) {
            float e0 = __expf(__ldcs(ip + ((unsigned)(i * 8 + 2 * jj)     << 14)));
            float e1 = __expf(__ldcs(ip + ((unsigned)(i * 8 + 2 * jj + 1) << 14)));
            m += e0 + e1;
            h[jj] = __floats2half2_rn(e0, e1);
        }
        uint4 q;
        q.x = *reinterpret_cast<unsigned*>(&h[0]);
        q.y = *reinterpret_cast<unsigned*>(&h[1]);
        q.z = *reinterpret_cast<unsigned*>(&h[2]);
        q.w = *reinterpret_cast<unsigned*>(&h[3]);
        ep4[i] = q;
        g_M[mb + ((unsigned)i << 14)] = __float2half_rn(m);
        g_R[mb + ((unsigned)i << 14)] = 1.f;
        g_C[mb + ((unsigned)i << 14)] = 1.f;
    }
}

// ---------------------------------------------------------------------------
// Fused half-iteration (all 32 batches).
// TRANS = 1: row = conv(M); R /= row+eps; N_j(fp16) = C_j * sum_i E_ij R_i
// TRANS = 0: col = conv(N); C /= col+eps; M_i(fp16) = R_i * sum_j E_ij C_j
// ---------------------------------------------------------------------------
template <int TRANS>
__global__ void __launch_bounds__(TPB) k_step(const float* __restrict__ kern)
{
    __shared__ float s_in[8 * 12 * 40];
    __shared__ float s_h[8 * 12 * 32];

    unsigned tid = threadIdx.x;
    unsigned tx = tid & 31u, ty = tid >> 5;
    unsigned blk = blockIdx.x;
    unsigned b  = blk >> 6;
    unsigned h0 = ((blk >> 2) & 15u) << 3;
    unsigned w0 = (blk & 3u) << 5;
    unsigned p  = ((h0 + ty) << 7) + (w0 + tx);
    unsigned mb = (b << 17) + p;

    float ax[5], ay[5];
    load_taps(kern, ax, ay);

    float*        vecA   = (TRANS ? g_R : g_C);
    const float*  vecB   = (TRANS ? g_C : g_R);
    __half*       outM   = (TRANS ? g_N : g_M);
    const __half* convIn = (TRANS ? g_M : g_N) + ((size_t)b << 17);

    float cv[8];
    conv8h(convIn, tid, tx, ty, h0, w0, ax, ay, s_in, s_h, cv);

    float av[8];
#pragma unroll
    for (int i = 0; i < 8; ++i) {
        float a = __fdividef(vecA[mb + ((unsigned)i << 14)], cv[i] + EPSF);
        av[i] = a;
        vecA[mb + ((unsigned)i << 14)] = a;
    }

    const uint4* ep4 = reinterpret_cast<const uint4*>(g_Eh + ((size_t)(b * HW + p) << 5));
    float acc[8] = {0.f, 0.f, 0.f, 0.f, 0.f, 0.f, 0.f, 0.f};
#pragma unroll
    for (int i = 0; i < 8; ++i) {
        uint4 q = __ldg(ep4 + i);
        float2 f0 = __half22float2(*reinterpret_cast<__half2*>(&q.x));
        float2 f1 = __half22float2(*reinterpret_cast<__half2*>(&q.y));
        float2 f2 = __half22float2(*reinterpret_cast<__half2*>(&q.z));
        float2 f3 = __half22float2(*reinterpret_cast<__half2*>(&q.w));
        if (TRANS) {
            float r = av[i];                       // N_j += E_ij * R_i
            acc[0] = fmaf(f0.x, r, acc[0]);  acc[1] = fmaf(f0.y, r, acc[1]);
            acc[2] = fmaf(f1.x, r, acc[2]);  acc[3] = fmaf(f1.y, r, acc[3]);
            acc[4] = fmaf(f2.x, r, acc[4]);  acc[5] = fmaf(f2.y, r, acc[5]);
            acc[6] = fmaf(f3.x, r, acc[6]);  acc[7] = fmaf(f3.y, r, acc[7]);
        } else {                                   // M_i += E_ij * C_j
            float v;
            v  = fmaf(f0.x, av[0], f0.y * av[1]);
            v  = fmaf(f1.x, av[2], fmaf(f1.y, av[3], v));
            v  = fmaf(f2.x, av[4], fmaf(f2.y, av[5], v));
            v  = fmaf(f3.x, av[6], fmaf(f3.y, av[7], v));
            acc[i] = v;
        }
    }
#pragma unroll
    for (int k = 0; k < 8; ++k)
        outM[mb + ((unsigned)k << 14)] =
            __float2half_rn(vecB[mb + ((unsigned)k << 14)] * acc[k]);
}

// ---------------------------------------------------------------------------
// Epilogue: finish iteration 20's col step; out = exp(input)(fp32) * R * C + EPS.
// (exp(log(x+eps)) == x+eps to fp32 rounding.)
// ---------------------------------------------------------------------------
__global__ void __launch_bounds__(TPB) k_epi(const float* __restrict__ kern,
                                             const float* __restrict__ in,
                                             float* __restrict__ out)
{
    __shared__ float s_in[8 * 12 * 40];
    __shared__ float s_h[8 * 12 * 32];

    unsigned tid = threadIdx.x;
    unsigned tx = tid & 31u, ty = tid >> 5;
    unsigned blk = blockIdx.x;
    unsigned b  = blk >> 6;
    unsigned h0 = ((blk >> 2) & 15u) << 3;
    unsigned w0 = (blk & 3u) << 5;
    unsigned p  = ((h0 + ty) << 7) + (w0 + tx);
    unsigned mb = (b << 17) + p;

    float ax[5], ay[5];
    load_taps(kern, ax, ay);

    float colv[8];
    conv8h(g_N + ((size_t)b << 17), tid, tx, ty, h0, w0, ax, ay, s_in, s_h, colv);

    float cfin[8], rv[8];
#pragma unroll
    for (int j = 0; j < 8; ++j)
        cfin[j] = __fdividef(g_C[mb + ((unsigned)j << 14)], colv[j] + EPSF);
#pragma unroll
    for (int i = 0; i < 8; ++i)
        rv[i] = g_R[mb + ((unsigned)i << 14)];

    const float* ip = in  + ((size_t)b << 20) + p;
    float*       ob = out + ((size_t)b << 20) + p;
#pragma unroll
    for (int i = 0; i < 8; ++i) {
        float ri = rv[i];
#pragma unroll
        for (int j = 0; j < 8; ++j) {
            unsigned off = (unsigned)((i << 3) + j) << 14;
            float e = __expf(__ldcs(ip + off));      // fp32 E for output precision
            __stcs(ob + off, fmaf(e, ri * cfin[j], EPSF));
        }
    }
}

// ---------------------------------------------------------------------------
extern "C" void kernel_launch(void* const* d_in, const int* in_sizes, int n_in,
                              void* d_out, int out_size)
{
    (void)out_size;
    const float* in   = (const float*)d_in[0];
    const float* kern = (const float*)d_in[1];
    if (n_in >= 2 && in_sizes[0] == 25) {   // defensive input-order check
        const float* t = in; in = kern; kern = t;
    }
    float* out = (float*)d_out;

    k_first<<<GRID, TPB>>>(in);
    k_step<1><<<GRID, TPB>>>(kern);            // iter 1: col half
    for (int t = 1; t < NITER; ++t) {
        k_step<0><<<GRID, TPB>>>(kern);        // finish iter t col-update, next row marginal
        k_step<1><<<GRID, TPB>>>(kern);        // row-update + col marginal
    }
    k_epi<<<GRID, TPB>>>(kern, in, out);       // finish iter 20 col-update + output
}